// round 4
// baseline (speedup 1.0000x reference)
#include <cuda_runtime.h>
#include <math_constants.h>

// ChamferDistance: x (8,8192,3) f32, y (8,8192,3) f32 -> scalar f32.
// FMA-pipe bound brute force with packed fma.rn.f32x2 (FFMA2).
//   d^2(q,r) = qq + (rr - 2*dot(q,r)); queries pre-scaled by -2; qq added in reduce.
//   min(sqrt(v+EPS)) == sqrt(min(v)+EPS) -> one sqrt per point at the end.
// R4: explicit software pipelining of inner-loop LDS (2 ref-pairs in flight),
// split min accumulators, qq deferred to reduce kernel, launch_bounds(128,7).

#define BATCH   8
#define NPTS    8192
#define RSPLIT  4
#define TPB     128
#define U       4                              // queries per thread
#define QPB     (TPB * U)                      // 512 queries per block
#define QBLK    (BATCH * NPTS / QPB)           // 128
#define TR      128                            // reference points per smem tile
#define RCHUNK  (NPTS / RSPLIT)                // 2048
#define NTILES  (RCHUNK / TR)                  // 16
#define EPS_F   1e-10f

__device__ float g_minpart[2][RSPLIT][BATCH * NPTS];
__device__ float g_partial[128];

__device__ __forceinline__ unsigned long long f2_fma(unsigned long long a, unsigned long long b, unsigned long long c) {
    unsigned long long d;
    asm("fma.rn.f32x2 %0, %1, %2, %3;" : "=l"(d) : "l"(a), "l"(b), "l"(c));
    return d;
}
__device__ __forceinline__ unsigned long long f2_pack(float a, float b) {
    unsigned long long r;
    asm("mov.b64 %0, {%1, %2};" : "=l"(r) : "f"(a), "f"(b));
    return r;
}
__device__ __forceinline__ void f2_unpack(unsigned long long v, float& lo, float& hi) {
    asm("mov.b64 {%0, %1}, %2;" : "=f"(lo), "=f"(hi) : "l"(v));
}

__global__ __launch_bounds__(TPB, 7)
void chamfer_pass_kernel(const float* __restrict__ x, const float* __restrict__ y) {
    const int dir = blockIdx.z;
    const float* __restrict__ Q = dir ? y : x;   // query side
    const float* __restrict__ R = dir ? x : y;   // reference side

    const int qbase = blockIdx.x * QPB;          // within one batch (16 blocks/batch)
    const int b     = qbase / NPTS;
    const int r0    = blockIdx.y * RCHUNK;
    const int t     = threadIdx.x;

    // Double-buffered pair-interleaved tiles (+16 floats pad for pipelined over-read):
    //   sm[buf][8j+0..1]=x pair, [8j+2..3]=y pair, [8j+4..5]=z pair, [8j+6..7]=rr pair
    __shared__ float sm[2][TR * 4 + 16];

    float minLo[U], minHi[U];
    unsigned long long qx2[U], qy2[U], qz2[U];   // query coords pre-scaled by -2, splatted
#pragma unroll
    for (int u = 0; u < U; u++) {
        const float* p = Q + (size_t)(qbase + u * TPB + t) * 3;
        float a = p[0] * -2.0f, c = p[1] * -2.0f, e = p[2] * -2.0f;
        qx2[u] = f2_pack(a, a);
        qy2[u] = f2_pack(c, c);
        qz2[u] = f2_pack(e, e);
        minLo[u] = CUDART_INF_F;
        minHi[u] = CUDART_INF_F;
    }

    const float* __restrict__ Rb = R + (size_t)b * NPTS * 3;
    const int jj = (t >> 1) * 8 + (t & 1);       // interleave slot for this thread's ref point

    // Prologue: stage tile 0 into buf 0.
    float rx, ry, rz;
    {
        const float* rp = Rb + (size_t)(r0 + t) * 3;   // TR == TPB
        rx = rp[0]; ry = rp[1]; rz = rp[2];
        sm[0][jj + 0] = rx;
        sm[0][jj + 2] = ry;
        sm[0][jj + 4] = rz;
        sm[0][jj + 6] = rx * rx + ry * ry + rz * rz;
    }
    __syncthreads();

#pragma unroll 1
    for (int tile = 0; tile < NTILES; tile++) {
        // Prefetch next tile from gmem (latency hidden behind this tile's compute)
        if (tile + 1 < NTILES) {
            const float* rp = Rb + (size_t)(r0 + (tile + 1) * TR + t) * 3;
            rx = rp[0]; ry = rp[1]; rz = rp[2];
        }

        const float* smc = sm[tile & 1];

        // Software-pipelined inner loop: 2 ref-pairs per step, next step's LDS in flight.
        ulonglong2 A0 = *reinterpret_cast<const ulonglong2*>(&smc[0]);
        ulonglong2 B0 = *reinterpret_cast<const ulonglong2*>(&smc[4]);
        ulonglong2 A1 = *reinterpret_cast<const ulonglong2*>(&smc[8]);
        ulonglong2 B1 = *reinterpret_cast<const ulonglong2*>(&smc[12]);

#pragma unroll 4
        for (int s = 0; s < TR / 4; s++) {
            const float* nx = &smc[(s + 1) * 16];   // last iter over-reads into pad
            ulonglong2 A2 = *reinterpret_cast<const ulonglong2*>(nx + 0);
            ulonglong2 B2 = *reinterpret_cast<const ulonglong2*>(nx + 4);
            ulonglong2 A3 = *reinterpret_cast<const ulonglong2*>(nx + 8);
            ulonglong2 B3 = *reinterpret_cast<const ulonglong2*>(nx + 12);

#pragma unroll
            for (int u = 0; u < U; u++) {
                unsigned long long acc = f2_fma(qx2[u], A0.x, B0.y);  // rr - 2 qx rx
                acc = f2_fma(qy2[u], A0.y, acc);
                acc = f2_fma(qz2[u], B0.x, acc);                      // rr - 2 dot
                float lo, hi;
                f2_unpack(acc, lo, hi);
                minLo[u] = fminf(minLo[u], lo);
                minHi[u] = fminf(minHi[u], hi);
            }
#pragma unroll
            for (int u = 0; u < U; u++) {
                unsigned long long acc = f2_fma(qx2[u], A1.x, B1.y);
                acc = f2_fma(qy2[u], A1.y, acc);
                acc = f2_fma(qz2[u], B1.x, acc);
                float lo, hi;
                f2_unpack(acc, lo, hi);
                minLo[u] = fminf(minLo[u], lo);
                minHi[u] = fminf(minHi[u], hi);
            }
            A0 = A2; B0 = B2; A1 = A3; B1 = B3;
        }

        if (tile + 1 < NTILES) {
            float* smn = sm[(tile + 1) & 1];
            smn[jj + 0] = rx;
            smn[jj + 2] = ry;
            smn[jj + 4] = rz;
            smn[jj + 6] = rx * rx + ry * ry + rz * rz;
            __syncthreads();
        }
    }

#pragma unroll
    for (int u = 0; u < U; u++) {
        g_minpart[dir][blockIdx.y][qbase + u * TPB + t] = fminf(minLo[u], minHi[u]);
    }
}

// 128 blocks: dir(2) x batch(8) x chunk(8); each covers 1024 queries.
// Adds the deferred qq term before the sqrt.
__global__ __launch_bounds__(256)
void chamfer_reduce_kernel(const float* __restrict__ x, const float* __restrict__ y) {
    const int dir   = blockIdx.x >> 6;
    const int b     = (blockIdx.x >> 3) & 7;
    const int chunk = blockIdx.x & 7;
    const int t     = threadIdx.x;
    const float* __restrict__ Qside = dir ? y : x;

    float s = 0.0f;
#pragma unroll
    for (int k = 0; k < 4; k++) {
        const int q = b * NPTS + chunk * 1024 + k * 256 + t;
        float v = g_minpart[dir][0][q];
#pragma unroll
        for (int r = 1; r < RSPLIT; r++) v = fminf(v, g_minpart[dir][r][q]);
        const float* p = Qside + (size_t)q * 3;
        float qq = p[0] * p[0] + p[1] * p[1] + p[2] * p[2];
        s += sqrtf(v + qq + EPS_F);
    }

    __shared__ float red[256];
    red[t] = s;
    __syncthreads();
    for (int o = 128; o > 0; o >>= 1) {
        if (t < o) red[t] += red[t + o];
        __syncthreads();
    }
    if (t == 0) g_partial[blockIdx.x] = red[0];
}

__global__ void chamfer_final_kernel(float* __restrict__ out) {
    float s = 0.0f;
#pragma unroll
    for (int b = 0; b < BATCH; b++) {
        float m0 = 0.0f, m1 = 0.0f;
#pragma unroll
        for (int c = 0; c < 8; c++) {
            m0 += g_partial[(0 << 6) | (b << 3) | c];
            m1 += g_partial[(1 << 6) | (b << 3) | c];
        }
        s += fmaxf(m0, m1) * (1.0f / (float)NPTS);
    }
    *out = s;
}

extern "C" void kernel_launch(void* const* d_in, const int* in_sizes, int n_in,
                              void* d_out, int out_size) {
    const float* x = (const float*)d_in[0];
    const float* y = (const float*)d_in[1];
    float* out = (float*)d_out;

    dim3 grid(QBLK, RSPLIT, 2);
    chamfer_pass_kernel<<<grid, TPB>>>(x, y);
    chamfer_reduce_kernel<<<128, 256>>>(x, y);
    chamfer_final_kernel<<<1, 1>>>(out);
}

// round 5
// speedup vs baseline: 1.0620x; 1.0620x over previous
#include <cuda_runtime.h>
#include <math_constants.h>

// ChamferDistance: x (8,8192,3) f32, y (8,8192,3) f32 -> scalar f32.
// FMA-pipe bound brute force with packed fma.rn.f32x2 (FFMA2).
//   d^2(q,r) = qq + (rr - 2*dot(q,r)); queries pre-scaled by -2; qq added in reduce.
//   min(sqrt(v+EPS)) == sqrt(min(v)+EPS) -> one sqrt per point at the end.
// R5: revert to R2's simple inner loop (no SW pipelining), TPB=256 with
// launch_bounds(256,5) for 40 resident warps/SM; split min accumulators.

#define BATCH   8
#define NPTS    8192
#define RSPLIT  8
#define TPB     256
#define U       4                              // queries per thread
#define QPB     (TPB * U)                      // 1024 queries per block
#define QBLK    (BATCH * NPTS / QPB)           // 64
#define TR      256                            // reference points per smem tile
#define RCHUNK  (NPTS / RSPLIT)                // 1024
#define NTILES  (RCHUNK / TR)                  // 4
#define EPS_F   1e-10f

__device__ float g_minpart[2][RSPLIT][BATCH * NPTS];
__device__ float g_partial[128];

__device__ __forceinline__ unsigned long long f2_fma(unsigned long long a, unsigned long long b, unsigned long long c) {
    unsigned long long d;
    asm("fma.rn.f32x2 %0, %1, %2, %3;" : "=l"(d) : "l"(a), "l"(b), "l"(c));
    return d;
}
__device__ __forceinline__ unsigned long long f2_pack(float a, float b) {
    unsigned long long r;
    asm("mov.b64 %0, {%1, %2};" : "=l"(r) : "f"(a), "f"(b));
    return r;
}
__device__ __forceinline__ void f2_unpack(unsigned long long v, float& lo, float& hi) {
    asm("mov.b64 {%0, %1}, %2;" : "=f"(lo), "=f"(hi) : "l"(v));
}

__global__ __launch_bounds__(TPB, 5)
void chamfer_pass_kernel(const float* __restrict__ x, const float* __restrict__ y) {
    const int dir = blockIdx.z;
    const float* __restrict__ Q = dir ? y : x;   // query side
    const float* __restrict__ R = dir ? x : y;   // reference side

    const int qbase = blockIdx.x * QPB;          // within one batch (8 blocks/batch)
    const int b     = qbase / NPTS;
    const int r0    = blockIdx.y * RCHUNK;
    const int t     = threadIdx.x;

    // Pair-interleaved tile: for ref pair j (points 2j, 2j+1):
    //   sm[8j+0..1]=x pair, [8j+2..3]=y pair, [8j+4..5]=z pair, [8j+6..7]=rr pair
    __shared__ float sm[TR * 4];

    float minLo[U], minHi[U];
    unsigned long long qx2[U], qy2[U], qz2[U];   // query coords pre-scaled by -2, splatted
#pragma unroll
    for (int u = 0; u < U; u++) {
        const float* p = Q + (size_t)(qbase + u * TPB + t) * 3;
        float a = p[0] * -2.0f, c = p[1] * -2.0f, e = p[2] * -2.0f;
        qx2[u] = f2_pack(a, a);
        qy2[u] = f2_pack(c, c);
        qz2[u] = f2_pack(e, e);
        minLo[u] = CUDART_INF_F;
        minHi[u] = CUDART_INF_F;
    }

    const float* __restrict__ Rb = R + (size_t)b * NPTS * 3;
    const int jj = (t >> 1) * 8 + (t & 1);       // interleave slot for this thread's ref point

#pragma unroll 1
    for (int tile = 0; tile < NTILES; tile++) {
        __syncthreads();
        {
            const float* rp = Rb + (size_t)(r0 + tile * TR + t) * 3;   // TR == TPB
            float rx = rp[0], ry = rp[1], rz = rp[2];
            sm[jj + 0] = rx;
            sm[jj + 2] = ry;
            sm[jj + 4] = rz;
            sm[jj + 6] = rx * rx + ry * ry + rz * rz;
        }
        __syncthreads();

#pragma unroll 8
        for (int j = 0; j < TR / 2; j++) {
            // Two LDS.128 -> four pre-packed f32x2 operands (broadcast, conflict-free)
            ulonglong2 A  = *reinterpret_cast<const ulonglong2*>(&sm[8 * j]);      // {x-pair, y-pair}
            ulonglong2 Bv = *reinterpret_cast<const ulonglong2*>(&sm[8 * j + 4]);  // {z-pair, rr-pair}
#pragma unroll
            for (int u = 0; u < U; u++) {
                unsigned long long acc = f2_fma(qx2[u], A.x, Bv.y);  // rr - 2 qx rx
                acc = f2_fma(qy2[u], A.y, acc);
                acc = f2_fma(qz2[u], Bv.x, acc);                     // rr - 2 dot (packed x2)
                float lo, hi;
                f2_unpack(acc, lo, hi);
                minLo[u] = fminf(minLo[u], lo);
                minHi[u] = fminf(minHi[u], hi);
            }
        }
    }

#pragma unroll
    for (int u = 0; u < U; u++) {
        g_minpart[dir][blockIdx.y][qbase + u * TPB + t] = fminf(minLo[u], minHi[u]);
    }
}

// 128 blocks: dir(2) x batch(8) x chunk(8); each covers 1024 queries.
// Adds the deferred qq term before the sqrt.
__global__ __launch_bounds__(256)
void chamfer_reduce_kernel(const float* __restrict__ x, const float* __restrict__ y) {
    const int dir   = blockIdx.x >> 6;
    const int b     = (blockIdx.x >> 3) & 7;
    const int chunk = blockIdx.x & 7;
    const int t     = threadIdx.x;
    const float* __restrict__ Qside = dir ? y : x;

    float s = 0.0f;
#pragma unroll
    for (int k = 0; k < 4; k++) {
        const int q = b * NPTS + chunk * 1024 + k * 256 + t;
        float v = g_minpart[dir][0][q];
#pragma unroll
        for (int r = 1; r < RSPLIT; r++) v = fminf(v, g_minpart[dir][r][q]);
        const float* p = Qside + (size_t)q * 3;
        float qq = p[0] * p[0] + p[1] * p[1] + p[2] * p[2];
        s += sqrtf(v + qq + EPS_F);
    }

    __shared__ float red[256];
    red[t] = s;
    __syncthreads();
    for (int o = 128; o > 0; o >>= 1) {
        if (t < o) red[t] += red[t + o];
        __syncthreads();
    }
    if (t == 0) g_partial[blockIdx.x] = red[0];
}

__global__ void chamfer_final_kernel(float* __restrict__ out) {
    float s = 0.0f;
#pragma unroll
    for (int b = 0; b < BATCH; b++) {
        float m0 = 0.0f, m1 = 0.0f;
#pragma unroll
        for (int c = 0; c < 8; c++) {
            m0 += g_partial[(0 << 6) | (b << 3) | c];
            m1 += g_partial[(1 << 6) | (b << 3) | c];
        }
        s += fmaxf(m0, m1) * (1.0f / (float)NPTS);
    }
    *out = s;
}

extern "C" void kernel_launch(void* const* d_in, const int* in_sizes, int n_in,
                              void* d_out, int out_size) {
    const float* x = (const float*)d_in[0];
    const float* y = (const float*)d_in[1];
    float* out = (float*)d_out;

    dim3 grid(QBLK, RSPLIT, 2);
    chamfer_pass_kernel<<<grid, TPB>>>(x, y);
    chamfer_reduce_kernel<<<128, 256>>>(x, y);
    chamfer_final_kernel<<<1, 1>>>(out);
}

// round 6
// speedup vs baseline: 1.0937x; 1.0299x over previous
#include <cuda_runtime.h>
#include <math_constants.h>

// ChamferDistance: x (8,8192,3) f32, y (8,8192,3) f32 -> scalar f32.
// FMA-pipe/issue bound brute force with packed fma.rn.f32x2 (FFMA2).
//   d^2(q,r) = qq + (rr - 2*dot(q,r)); queries pre-scaled by -2; qq added in reduce.
//   min(sqrt(v+EPS)) == sqrt(min(v)+EPS) -> one sqrt per point at the end.
// R6: anti-tail grid. TPB=128 / 10 blocks/SM (62.5% occ cap) with RSPLIT=16
// -> 4096 fine-grained blocks (2.77 waves, last wave 77% full) instead of a
// 2-wave grid with a 40%-idle second wave. Inner loop = proven R2 shape.

#define BATCH   8
#define NPTS    8192
#define RSPLIT  16
#define TPB     128
#define U       4                              // queries per thread
#define QPB     (TPB * U)                      // 512 queries per block
#define QBLK    (BATCH * NPTS / QPB)           // 128
#define TR      128                            // reference points per smem tile
#define RCHUNK  (NPTS / RSPLIT)                // 512
#define NTILES  (RCHUNK / TR)                  // 4
#define EPS_F   1e-10f

__device__ float g_minpart[2][RSPLIT][BATCH * NPTS];
__device__ float g_partial[128];

__device__ __forceinline__ unsigned long long f2_fma(unsigned long long a, unsigned long long b, unsigned long long c) {
    unsigned long long d;
    asm("fma.rn.f32x2 %0, %1, %2, %3;" : "=l"(d) : "l"(a), "l"(b), "l"(c));
    return d;
}
__device__ __forceinline__ unsigned long long f2_pack(float a, float b) {
    unsigned long long r;
    asm("mov.b64 %0, {%1, %2};" : "=l"(r) : "f"(a), "f"(b));
    return r;
}
__device__ __forceinline__ void f2_unpack(unsigned long long v, float& lo, float& hi) {
    asm("mov.b64 {%0, %1}, %2;" : "=f"(lo), "=f"(hi) : "l"(v));
}

__global__ __launch_bounds__(TPB, 10)
void chamfer_pass_kernel(const float* __restrict__ x, const float* __restrict__ y) {
    const int dir = blockIdx.z;
    const float* __restrict__ Q = dir ? y : x;   // query side
    const float* __restrict__ R = dir ? x : y;   // reference side

    const int qbase = blockIdx.x * QPB;          // within one batch (16 blocks/batch)
    const int b     = qbase / NPTS;
    const int r0    = blockIdx.y * RCHUNK;
    const int t     = threadIdx.x;

    // Pair-interleaved tile: for ref pair j (points 2j, 2j+1):
    //   sm[8j+0..1]=x pair, [8j+2..3]=y pair, [8j+4..5]=z pair, [8j+6..7]=rr pair
    __shared__ float sm[TR * 4];

    float minLo[U], minHi[U];
    unsigned long long qx2[U], qy2[U], qz2[U];   // query coords pre-scaled by -2, splatted
#pragma unroll
    for (int u = 0; u < U; u++) {
        const float* p = Q + (size_t)(qbase + u * TPB + t) * 3;
        float a = p[0] * -2.0f, c = p[1] * -2.0f, e = p[2] * -2.0f;
        qx2[u] = f2_pack(a, a);
        qy2[u] = f2_pack(c, c);
        qz2[u] = f2_pack(e, e);
        minLo[u] = CUDART_INF_F;
        minHi[u] = CUDART_INF_F;
    }

    const float* __restrict__ Rb = R + (size_t)b * NPTS * 3;
    const int jj = (t >> 1) * 8 + (t & 1);       // interleave slot for this thread's ref point

#pragma unroll 1
    for (int tile = 0; tile < NTILES; tile++) {
        __syncthreads();
        {
            const float* rp = Rb + (size_t)(r0 + tile * TR + t) * 3;   // TR == TPB
            float rx = rp[0], ry = rp[1], rz = rp[2];
            sm[jj + 0] = rx;
            sm[jj + 2] = ry;
            sm[jj + 4] = rz;
            sm[jj + 6] = rx * rx + ry * ry + rz * rz;
        }
        __syncthreads();

#pragma unroll 16
        for (int j = 0; j < TR / 2; j++) {
            // Two LDS.128 -> four pre-packed f32x2 operands (broadcast, conflict-free)
            ulonglong2 A  = *reinterpret_cast<const ulonglong2*>(&sm[8 * j]);      // {x-pair, y-pair}
            ulonglong2 Bv = *reinterpret_cast<const ulonglong2*>(&sm[8 * j + 4]);  // {z-pair, rr-pair}
#pragma unroll
            for (int u = 0; u < U; u++) {
                unsigned long long acc = f2_fma(qx2[u], A.x, Bv.y);  // rr - 2 qx rx
                acc = f2_fma(qy2[u], A.y, acc);
                acc = f2_fma(qz2[u], Bv.x, acc);                     // rr - 2 dot (packed x2)
                float lo, hi;
                f2_unpack(acc, lo, hi);
                minLo[u] = fminf(minLo[u], lo);
                minHi[u] = fminf(minHi[u], hi);
            }
        }
    }

#pragma unroll
    for (int u = 0; u < U; u++) {
        g_minpart[dir][blockIdx.y][qbase + u * TPB + t] = fminf(minLo[u], minHi[u]);
    }
}

// 128 blocks: dir(2) x batch(8) x chunk(8); each covers 1024 queries.
// Adds the deferred qq term before the sqrt.
__global__ __launch_bounds__(256)
void chamfer_reduce_kernel(const float* __restrict__ x, const float* __restrict__ y) {
    const int dir   = blockIdx.x >> 6;
    const int b     = (blockIdx.x >> 3) & 7;
    const int chunk = blockIdx.x & 7;
    const int t     = threadIdx.x;
    const float* __restrict__ Qside = dir ? y : x;

    float s = 0.0f;
#pragma unroll
    for (int k = 0; k < 4; k++) {
        const int q = b * NPTS + chunk * 1024 + k * 256 + t;
        float v = g_minpart[dir][0][q];
#pragma unroll
        for (int r = 1; r < RSPLIT; r++) v = fminf(v, g_minpart[dir][r][q]);
        const float* p = Qside + (size_t)q * 3;
        float qq = p[0] * p[0] + p[1] * p[1] + p[2] * p[2];
        s += sqrtf(v + qq + EPS_F);
    }

    __shared__ float red[256];
    red[t] = s;
    __syncthreads();
    for (int o = 128; o > 0; o >>= 1) {
        if (t < o) red[t] += red[t + o];
        __syncthreads();
    }
    if (t == 0) g_partial[blockIdx.x] = red[0];
}

__global__ void chamfer_final_kernel(float* __restrict__ out) {
    float s = 0.0f;
#pragma unroll
    for (int b = 0; b < BATCH; b++) {
        float m0 = 0.0f, m1 = 0.0f;
#pragma unroll
        for (int c = 0; c < 8; c++) {
            m0 += g_partial[(0 << 6) | (b << 3) | c];
            m1 += g_partial[(1 << 6) | (b << 3) | c];
        }
        s += fmaxf(m0, m1) * (1.0f / (float)NPTS);
    }
    *out = s;
}

extern "C" void kernel_launch(void* const* d_in, const int* in_sizes, int n_in,
                              void* d_out, int out_size) {
    const float* x = (const float*)d_in[0];
    const float* y = (const float*)d_in[1];
    float* out = (float*)d_out;

    dim3 grid(QBLK, RSPLIT, 2);
    chamfer_pass_kernel<<<grid, TPB>>>(x, y);
    chamfer_reduce_kernel<<<128, 256>>>(x, y);
    chamfer_final_kernel<<<1, 1>>>(out);
}

// round 7
// speedup vs baseline: 1.1208x; 1.0247x over previous
#include <cuda_runtime.h>
#include <math_constants.h>

// ChamferDistance: x (8,8192,3) f32, y (8,8192,3) f32 -> scalar f32.
// FMA-pipe bound brute force with packed fma.rn.f32x2 (FFMA2).
//   d^2(q,r) = qq + (rr - 2*dot(q,r)); queries pre-scaled by -2; qq added in reduce.
//   min(sqrt(v+EPS)) == sqrt(min(v)+EPS) -> one sqrt per point at the end.
// R7: U=8 queries/thread -> halves LDS-per-fma-cycle (smem crossbar was the
// structural ~62% fma ceiling: 2 LDS.128 per 24 fma-cyc at 4cyc/LDS effective).
// Single min accumulator per query; launch_bounds(128,6); RSPLIT=16.

#define BATCH   8
#define NPTS    8192
#define RSPLIT  16
#define TPB     128
#define U       8                              // queries per thread
#define QPB     (TPB * U)                      // 1024 queries per block
#define QBLK    (BATCH * NPTS / QPB)           // 64
#define TR      128                            // reference points per smem tile
#define RCHUNK  (NPTS / RSPLIT)                // 512
#define NTILES  (RCHUNK / TR)                  // 4
#define EPS_F   1e-10f

__device__ float g_minpart[2][RSPLIT][BATCH * NPTS];
__device__ float g_partial[128];

__device__ __forceinline__ unsigned long long f2_fma(unsigned long long a, unsigned long long b, unsigned long long c) {
    unsigned long long d;
    asm("fma.rn.f32x2 %0, %1, %2, %3;" : "=l"(d) : "l"(a), "l"(b), "l"(c));
    return d;
}
__device__ __forceinline__ unsigned long long f2_pack(float a, float b) {
    unsigned long long r;
    asm("mov.b64 %0, {%1, %2};" : "=l"(r) : "f"(a), "f"(b));
    return r;
}
__device__ __forceinline__ void f2_unpack(unsigned long long v, float& lo, float& hi) {
    asm("mov.b64 {%0, %1}, %2;" : "=f"(lo), "=f"(hi) : "l"(v));
}

__global__ __launch_bounds__(TPB, 6)
void chamfer_pass_kernel(const float* __restrict__ x, const float* __restrict__ y) {
    const int dir = blockIdx.z;
    const float* __restrict__ Q = dir ? y : x;   // query side
    const float* __restrict__ R = dir ? x : y;   // reference side

    const int qbase = blockIdx.x * QPB;          // within one batch (8 blocks/batch)
    const int b     = qbase / NPTS;
    const int r0    = blockIdx.y * RCHUNK;
    const int t     = threadIdx.x;

    // Pair-interleaved tile: for ref pair j (points 2j, 2j+1):
    //   sm[8j+0..1]=x pair, [8j+2..3]=y pair, [8j+4..5]=z pair, [8j+6..7]=rr pair
    __shared__ float sm[TR * 4];

    float minv[U];
    unsigned long long qx2[U], qy2[U], qz2[U];   // query coords pre-scaled by -2, splatted
#pragma unroll
    for (int u = 0; u < U; u++) {
        const float* p = Q + (size_t)(qbase + u * TPB + t) * 3;
        float a = p[0] * -2.0f, c = p[1] * -2.0f, e = p[2] * -2.0f;
        qx2[u] = f2_pack(a, a);
        qy2[u] = f2_pack(c, c);
        qz2[u] = f2_pack(e, e);
        minv[u] = CUDART_INF_F;
    }

    const float* __restrict__ Rb = R + (size_t)b * NPTS * 3;
    const int jj = (t >> 1) * 8 + (t & 1);       // interleave slot for this thread's ref point

#pragma unroll 1
    for (int tile = 0; tile < NTILES; tile++) {
        __syncthreads();
        {
            const float* rp = Rb + (size_t)(r0 + tile * TR + t) * 3;   // TR == TPB
            float rx = rp[0], ry = rp[1], rz = rp[2];
            sm[jj + 0] = rx;
            sm[jj + 2] = ry;
            sm[jj + 4] = rz;
            sm[jj + 6] = rx * rx + ry * ry + rz * rz;
        }
        __syncthreads();

#pragma unroll 4
        for (int j = 0; j < TR / 2; j++) {
            // Two LDS.128 -> four pre-packed f32x2 operands (broadcast, conflict-free),
            // each pair reused by 8 queries -> LDS rate no longer binds the crossbar.
            ulonglong2 A  = *reinterpret_cast<const ulonglong2*>(&sm[8 * j]);      // {x-pair, y-pair}
            ulonglong2 Bv = *reinterpret_cast<const ulonglong2*>(&sm[8 * j + 4]);  // {z-pair, rr-pair}
#pragma unroll
            for (int u = 0; u < U; u++) {
                unsigned long long acc = f2_fma(qx2[u], A.x, Bv.y);  // rr - 2 qx rx
                acc = f2_fma(qy2[u], A.y, acc);
                acc = f2_fma(qz2[u], Bv.x, acc);                     // rr - 2 dot (packed x2)
                float lo, hi;
                f2_unpack(acc, lo, hi);
                minv[u] = fminf(minv[u], fminf(lo, hi));
            }
        }
    }

#pragma unroll
    for (int u = 0; u < U; u++) {
        g_minpart[dir][blockIdx.y][qbase + u * TPB + t] = minv[u];
    }
}

// 128 blocks: dir(2) x batch(8) x chunk(8); each covers 1024 queries.
// Adds the deferred qq term before the sqrt.
__global__ __launch_bounds__(256)
void chamfer_reduce_kernel(const float* __restrict__ x, const float* __restrict__ y) {
    const int dir   = blockIdx.x >> 6;
    const int b     = (blockIdx.x >> 3) & 7;
    const int chunk = blockIdx.x & 7;
    const int t     = threadIdx.x;
    const float* __restrict__ Qside = dir ? y : x;

    float s = 0.0f;
#pragma unroll
    for (int k = 0; k < 4; k++) {
        const int q = b * NPTS + chunk * 1024 + k * 256 + t;
        float v = g_minpart[dir][0][q];
#pragma unroll
        for (int r = 1; r < RSPLIT; r++) v = fminf(v, g_minpart[dir][r][q]);
        const float* p = Qside + (size_t)q * 3;
        float qq = p[0] * p[0] + p[1] * p[1] + p[2] * p[2];
        s += sqrtf(v + qq + EPS_F);
    }

    __shared__ float red[256];
    red[t] = s;
    __syncthreads();
    for (int o = 128; o > 0; o >>= 1) {
        if (t < o) red[t] += red[t + o];
        __syncthreads();
    }
    if (t == 0) g_partial[blockIdx.x] = red[0];
}

__global__ void chamfer_final_kernel(float* __restrict__ out) {
    float s = 0.0f;
#pragma unroll
    for (int b = 0; b < BATCH; b++) {
        float m0 = 0.0f, m1 = 0.0f;
#pragma unroll
        for (int c = 0; c < 8; c++) {
            m0 += g_partial[(0 << 6) | (b << 3) | c];
            m1 += g_partial[(1 << 6) | (b << 3) | c];
        }
        s += fmaxf(m0, m1) * (1.0f / (float)NPTS);
    }
    *out = s;
}

extern "C" void kernel_launch(void* const* d_in, const int* in_sizes, int n_in,
                              void* d_out, int out_size) {
    const float* x = (const float*)d_in[0];
    const float* y = (const float*)d_in[1];
    float* out = (float*)d_out;

    dim3 grid(QBLK, RSPLIT, 2);
    chamfer_pass_kernel<<<grid, TPB>>>(x, y);
    chamfer_reduce_kernel<<<128, 256>>>(x, y);
    chamfer_final_kernel<<<1, 1>>>(out);
}